// round 8
// baseline (speedup 1.0000x reference)
#include <cuda_runtime.h>
#include <cuda_bf16.h>
#include <math.h>
#include <stdint.h>

// conv_nonlinear R8: R7 + (1) dual accumulator chains (halve serial HMMA depth),
// (2) cheap bf16 split/pack via cvt.rn.bf16x2.f32 + shift-extract,
// (3) 448 threads / 14 warps (reg cap 146).
// mma.sync bf16, split-precision 3-pass: D = Ah*Bh + Al*Bh + Ah*Bl, fp32 accum.
// Activations register-resident (C-fragment == next A-fragment identity).

#define NB 16
#define NK 64
#define LSEQ 1000
#define NOUT 986
#define MTOT (NB*NOUT)     // 15776
#define NTILE (MTOT/16)    // 986
#define NTH 448
#define NWARP 14
#define NGRP 8
#define TPG 124            // tiles per CTA group (8*124 >= 986)

// Ktrue {60,72,86,86,71}  Ntrue {72,86,86,71,59}
// KSTEPS {4,5,6,6,5}  NT=Npad/8 {10,12,12,10,8}
// KW (weight row stride, elems; KW/8 odd -> conflict-free ldmatrix) {72,88,104,104,88}
#define WO0 0
#define WO1 5760
#define WO2 14208
#define WO3 24192
#define WO4 32512
#define WTOTAL 38144

#define SM_WHI  0
#define SM_WLO  (WTOTAL*2)          // 76288
#define SM_BIAS (WTOTAL*4)          // 152576
#define SM_HW   (SM_BIAS + 416*4)   // 154240
#define SMEM_TOTAL (SM_HW + 64*4)   // 154496

__device__ __nv_bfloat16 g_imh[MTOT * 64];
__device__ __nv_bfloat16 g_iml[MTOT * 64];

__device__ __forceinline__ uint32_t smem_u32(const void* p) {
    uint32_t a;
    asm("{ .reg .u64 t; cvta.to.shared.u64 t, %1; cvt.u32.u64 %0, t; }"
        : "=r"(a) : "l"(p));
    return a;
}
__device__ __forceinline__ float gelu_exact(float v) {
    return 0.5f * v * (1.0f + erff(v * 0.70710678118654752f));
}
__device__ __forceinline__ void split_bf16(float v, uint16_t& h, uint16_t& l) {
    __nv_bfloat16 hb = __float2bfloat16(v);
    float rem = v - __bfloat162float(hb);
    h = __bfloat16_as_ushort(hb);
    l = __bfloat16_as_ushort(__float2bfloat16(rem));
}
// pack (g0,g1) -> hi-bf16x2 and residual lo-bf16x2 in 6 ops
__device__ __forceinline__ void pack_split(float g0, float g1,
                                           uint32_t& hpk, uint32_t& lpk) {
    asm("cvt.rn.bf16x2.f32 %0, %1, %2;" : "=r"(hpk) : "f"(g1), "f"(g0));
    float h0f = __uint_as_float(hpk << 16);
    float h1f = __uint_as_float(hpk & 0xffff0000u);
    asm("cvt.rn.bf16x2.f32 %0, %1, %2;" : "=r"(lpk) : "f"(g1 - h1f), "f"(g0 - h0f));
}
__device__ __forceinline__ void ldm_x4(uint32_t* r, uint32_t addr) {
    asm volatile("ldmatrix.sync.aligned.m8n8.x4.shared.b16 {%0,%1,%2,%3}, [%4];"
                 : "=r"(r[0]), "=r"(r[1]), "=r"(r[2]), "=r"(r[3]) : "r"(addr));
}
__device__ __forceinline__ void ldm_x2(uint32_t& b0, uint32_t& b1, uint32_t addr) {
    asm volatile("ldmatrix.sync.aligned.m8n8.x2.shared.b16 {%0,%1}, [%2];"
                 : "=r"(b0), "=r"(b1) : "r"(addr));
}
__device__ __forceinline__ void mma16816(float& c0, float& c1, float& c2, float& c3,
                                         const uint32_t* a, uint32_t b0, uint32_t b1) {
    asm volatile(
        "mma.sync.aligned.m16n8k16.row.col.f32.bf16.bf16.f32 "
        "{%0,%1,%2,%3},{%4,%5,%6,%7},{%8,%9},{%0,%1,%2,%3};"
        : "+f"(c0), "+f"(c1), "+f"(c2), "+f"(c3)
        : "r"(a[0]), "r"(a[1]), "r"(a[2]), "r"(a[3]), "r"(b0), "r"(b1));
}

// ---------------- kernel 1: im2col + split ----------------
__global__ void __launch_bounds__(256)
im2col_kernel(const float* __restrict__ x) {
    int idx = blockIdx.x * 256 + threadIdx.x;
    if (idx >= MTOT * 64) return;
    int m = idx >> 6, c64 = idx & 63;
    float v = 0.0f;
    if (c64 < 60) {
        int c = c64 / 15, j = c64 - c * 15;
        int b = m / NOUT, p = m - b * NOUT;
        v = x[b * (4 * LSEQ) + c * LSEQ + p + j];
    }
    uint16_t h, l;
    split_bf16(v, h, l);
    g_imh[idx] = __ushort_as_bfloat16(h);
    g_iml[idx] = __ushort_as_bfloat16(l);
}

// ---------------- kernel 2 ----------------
__device__ __forceinline__ void stage_w(char* sm, const float* w,
                                        int Ktrue, int Ntrue, int Npad, int KW,
                                        int wo, int tid) {
    __nv_bfloat16* wh = reinterpret_cast<__nv_bfloat16*>(sm + SM_WHI) + wo;
    __nv_bfloat16* wl = reinterpret_cast<__nv_bfloat16*>(sm + SM_WLO) + wo;
    int n = Npad * KW;
    for (int i = tid; i < n; i += NTH) {
        int nn = i / KW, kk = i - nn * KW;
        float v = (nn < Ntrue && kk < Ktrue) ? w[kk * Ntrue + nn] : 0.0f;
        uint16_t h, l;
        split_bf16(v, h, l);
        wh[i] = __ushort_as_bfloat16(h);
        wl[i] = __ushort_as_bfloat16(l);
    }
}

// One layer, dual accumulator chains d (even work) / e (odd work).
template<int KS, int NT, int KW, bool LAST>
__device__ __forceinline__ void do_layer(const uint32_t ah[][4], const uint32_t al[][4],
                                         uint32_t anh[][4], uint32_t anl[][4],
                                         uint32_t whb, uint32_t wlb,
                                         const float* __restrict__ bias,
                                         const float* __restrict__ hw,
                                         int lane, float& p0, float& p1) {
    const uint32_t brow4 = (uint32_t)(lane & 7) * (KW * 2) + (uint32_t)(lane >> 3) * 16;
    const int col = 2 * (lane & 3);

    #pragma unroll
    for (int n = 0; n < NT; ++n) {
        float d0 = 0.f, d1 = 0.f, d2 = 0.f, d3 = 0.f;   // chain d
        float e0 = 0.f, e1 = 0.f, e2 = 0.f, e3 = 0.f;   // chain e
        const uint32_t bh = whb + (uint32_t)(n * 8) * (KW * 2) + brow4;
        const uint32_t bl = wlb + (uint32_t)(n * 8) * (KW * 2) + brow4;

        // hi-B pass: Ah->d, Al->e (same B regs, independent chains)
        #pragma unroll
        for (int p = 0; p < KS / 2; ++p) {
            uint32_t b[4];
            ldm_x4(b, bh + p * 64);
            mma16816(d0, d1, d2, d3, ah[2*p],     b[0], b[1]);
            mma16816(e0, e1, e2, e3, al[2*p],     b[0], b[1]);
            mma16816(d0, d1, d2, d3, ah[2*p + 1], b[2], b[3]);
            mma16816(e0, e1, e2, e3, al[2*p + 1], b[2], b[3]);
        }
        if (KS & 1) {
            uint32_t b0, b1;
            ldm_x2(b0, b1, bh + (KS - 1) * 32);
            mma16816(d0, d1, d2, d3, ah[KS - 1], b0, b1);
            mma16816(e0, e1, e2, e3, al[KS - 1], b0, b1);
        }
        // lo-B pass: Ah only, alternate chains
        #pragma unroll
        for (int p = 0; p < KS / 2; ++p) {
            uint32_t b[4];
            ldm_x4(b, bl + p * 64);
            mma16816(d0, d1, d2, d3, ah[2*p],     b[0], b[1]);
            mma16816(e0, e1, e2, e3, ah[2*p + 1], b[2], b[3]);
        }
        if (KS & 1) {
            uint32_t b0, b1;
            ldm_x2(b0, b1, bl + (KS - 1) * 32);
            mma16816(e0, e1, e2, e3, ah[KS - 1], b0, b1);
        }

        const int cg = n * 8 + col;
        const float bb0 = bias[cg], bb1 = bias[cg + 1];
        const float g0 = gelu_exact(d0 + e0 + bb0);
        const float g1 = gelu_exact(d1 + e1 + bb1);
        const float g2 = gelu_exact(d2 + e2 + bb0);
        const float g3 = gelu_exact(d3 + e3 + bb1);

        if (!LAST) {
            pack_split(g0, g1, anh[n / 2][(n & 1) * 2 + 0], anl[n / 2][(n & 1) * 2 + 0]);
            pack_split(g2, g3, anh[n / 2][(n & 1) * 2 + 1], anl[n / 2][(n & 1) * 2 + 1]);
        } else {
            p0 = fmaf(g0, hw[cg], fmaf(g1, hw[cg + 1], p0));
            p1 = fmaf(g2, hw[cg], fmaf(g3, hw[cg + 1], p1));
        }
    }
}

__global__ void __launch_bounds__(NTH, 1)
expert_kernel(const float* __restrict__ w0, const float* __restrict__ b0,
              const float* __restrict__ w1, const float* __restrict__ b1,
              const float* __restrict__ w2, const float* __restrict__ b2,
              const float* __restrict__ w3, const float* __restrict__ b3,
              const float* __restrict__ w4, const float* __restrict__ b4,
              const float* __restrict__ head_w, const float* __restrict__ head_b,
              float* __restrict__ out) {
    extern __shared__ char sm[];
    const uint32_t sb = smem_u32(sm);
    const int k = blockIdx.x;
    const int grp = blockIdx.y;
    const int tid = threadIdx.x;
    const int lane = tid & 31;
    const int wid = tid >> 5;

    {
        float* bm = reinterpret_cast<float*>(sm + SM_BIAS);
        const float* bs[5] = {b0, b1, b2, b3, b4};
        const int ntrue[5] = {72, 86, 86, 71, 59};
        const int npad[5] = {80, 96, 96, 80, 64};
        const int boff[5] = {0, 80, 176, 272, 352};
        #pragma unroll
        for (int L = 0; L < 5; ++L) {
            const float* src = bs[L] + k * ntrue[L];
            for (int i = tid; i < npad[L]; i += NTH)
                bm[boff[L] + i] = (i < ntrue[L]) ? src[i] : 0.0f;
        }
        float* hwm = reinterpret_cast<float*>(sm + SM_HW);
        for (int i = tid; i < 64; i += NTH)
            hwm[i] = (i < 59) ? head_w[i] : 0.0f;
    }
    stage_w(sm, w0 + k * 60 * 72, 60, 72, 80,  72, WO0, tid);
    stage_w(sm, w1 + k * 72 * 86, 72, 86, 96,  88, WO1, tid);
    stage_w(sm, w2 + k * 86 * 86, 86, 86, 96, 104, WO2, tid);
    stage_w(sm, w3 + k * 86 * 71, 86, 71, 80, 104, WO3, tid);
    stage_w(sm, w4 + k * 71 * 59, 71, 59, 64,  88, WO4, tid);
    __syncthreads();

    const float hb = head_b[0];
    const float* bm = reinterpret_cast<const float*>(sm + SM_BIAS);
    const float* hwm = reinterpret_cast<const float*>(sm + SM_HW);
    const int g = lane >> 2;
    const int col0 = 2 * (lane & 3);

    uint32_t A0h[6][4], A0l[6][4], A1h[6][4], A1l[6][4];

    for (int tt = wid; tt < TPG; tt += NWARP) {
        const int tile = grp * TPG + tt;
        if (tile >= NTILE) continue;
        const int m0 = tile * 16;

        {
            const char* h0p = (const char*)(g_imh + (m0 + g) * 64 + col0);
            const char* h8p = (const char*)(g_imh + (m0 + g + 8) * 64 + col0);
            const char* l0p = (const char*)(g_iml + (m0 + g) * 64 + col0);
            const char* l8p = (const char*)(g_iml + (m0 + g + 8) * 64 + col0);
            #pragma unroll
            for (int j = 0; j < 4; ++j) {
                A0h[j][0] = *(const uint32_t*)(h0p + j * 32);
                A0h[j][1] = *(const uint32_t*)(h8p + j * 32);
                A0h[j][2] = *(const uint32_t*)(h0p + j * 32 + 16);
                A0h[j][3] = *(const uint32_t*)(h8p + j * 32 + 16);
                A0l[j][0] = *(const uint32_t*)(l0p + j * 32);
                A0l[j][1] = *(const uint32_t*)(l8p + j * 32);
                A0l[j][2] = *(const uint32_t*)(l0p + j * 32 + 16);
                A0l[j][3] = *(const uint32_t*)(l8p + j * 32 + 16);
            }
        }

        float p0 = 0.0f, p1 = 0.0f;
        do_layer<4, 10,  72, false>(A0h, A0l, A1h, A1l,
            sb + SM_WHI + WO0 * 2, sb + SM_WLO + WO0 * 2, bm + 0,   hwm, lane, p0, p1);
        do_layer<5, 12,  88, false>(A1h, A1l, A0h, A0l,
            sb + SM_WHI + WO1 * 2, sb + SM_WLO + WO1 * 2, bm + 80,  hwm, lane, p0, p1);
        do_layer<6, 12, 104, false>(A0h, A0l, A1h, A1l,
            sb + SM_WHI + WO2 * 2, sb + SM_WLO + WO2 * 2, bm + 176, hwm, lane, p0, p1);
        do_layer<6, 10, 104, false>(A1h, A1l, A0h, A0l,
            sb + SM_WHI + WO3 * 2, sb + SM_WLO + WO3 * 2, bm + 272, hwm, lane, p0, p1);
        do_layer<5,  8,  88, true >(A0h, A0l, A1h, A1l,
            sb + SM_WHI + WO4 * 2, sb + SM_WLO + WO4 * 2, bm + 352, hwm, lane, p0, p1);

        p0 += __shfl_xor_sync(0xffffffffu, p0, 1);
        p0 += __shfl_xor_sync(0xffffffffu, p0, 2);
        p1 += __shfl_xor_sync(0xffffffffu, p1, 1);
        p1 += __shfl_xor_sync(0xffffffffu, p1, 2);
        if ((lane & 3) == 0) {
            int m = m0 + g;
            int b = m / NOUT, p = m - b * NOUT;
            out[(b * NK + k) * NOUT + p] = p0 + hb;
            m += 8;
            b = m / NOUT; p = m - b * NOUT;
            out[(b * NK + k) * NOUT + p] = p1 + hb;
        }
    }
}

extern "C" void kernel_launch(void* const* d_in, const int* in_sizes, int n_in,
                              void* d_out, int out_size) {
    const float* x      = (const float*)d_in[0];
    const float* w0     = (const float*)d_in[1];
    const float* b0     = (const float*)d_in[2];
    const float* w1     = (const float*)d_in[3];
    const float* b1     = (const float*)d_in[4];
    const float* w2     = (const float*)d_in[5];
    const float* b2     = (const float*)d_in[6];
    const float* w3     = (const float*)d_in[7];
    const float* b3     = (const float*)d_in[8];
    const float* w4     = (const float*)d_in[9];
    const float* b4     = (const float*)d_in[10];
    const float* head_w = (const float*)d_in[11];
    const float* head_b = (const float*)d_in[12];
    float* out = (float*)d_out;

    im2col_kernel<<<(MTOT * 64 + 255) / 256, 256>>>(x);

    cudaFuncSetAttribute(expert_kernel,
                         cudaFuncAttributeMaxDynamicSharedMemorySize, SMEM_TOTAL);
    dim3 grid(NK, NGRP);
    expert_kernel<<<grid, NTH, SMEM_TOTAL>>>(
        w0, b0, w1, b1, w2, b2, w3, b3, w4, b4, head_w, head_b, out);
}

// round 9
// speedup vs baseline: 1.0761x; 1.0761x over previous
#include <cuda_runtime.h>
#include <cuda_bf16.h>
#include <math.h>
#include <stdint.h>

// conv_nonlinear R9: R7 base (384 thr / 12 warps, regs<=170, no spill) +
// dual accumulator chains (halve serial HMMA depth) +
// cheap bf16 split/pack via cvt.rn.bf16x2.f32 + shift-extract.
// mma.sync bf16, split-precision 3-pass: D = Ah*Bh + Al*Bh + Ah*Bl, fp32 accum.
// Activations register-resident (C-fragment == next A-fragment identity).

#define NB 16
#define NK 64
#define LSEQ 1000
#define NOUT 986
#define MTOT (NB*NOUT)     // 15776
#define NTILE (MTOT/16)    // 986
#define NTH 384
#define NWARP 12
#define NGRP 8
#define TPG 124            // tiles per CTA group (8*124 >= 986)

// Ktrue {60,72,86,86,71}  Ntrue {72,86,86,71,59}
// KSTEPS {4,5,6,6,5}  NT=Npad/8 {10,12,12,10,8}
// KW (weight row stride, elems; KW/8 odd -> conflict-free ldmatrix) {72,88,104,104,88}
#define WO0 0
#define WO1 5760
#define WO2 14208
#define WO3 24192
#define WO4 32512
#define WTOTAL 38144

#define SM_WHI  0
#define SM_WLO  (WTOTAL*2)          // 76288
#define SM_BIAS (WTOTAL*4)          // 152576
#define SM_HW   (SM_BIAS + 416*4)   // 154240
#define SMEM_TOTAL (SM_HW + 64*4)   // 154496

__device__ __nv_bfloat16 g_imh[MTOT * 64];
__device__ __nv_bfloat16 g_iml[MTOT * 64];

__device__ __forceinline__ uint32_t smem_u32(const void* p) {
    uint32_t a;
    asm("{ .reg .u64 t; cvta.to.shared.u64 t, %1; cvt.u32.u64 %0, t; }"
        : "=r"(a) : "l"(p));
    return a;
}
__device__ __forceinline__ float gelu_exact(float v) {
    return 0.5f * v * (1.0f + erff(v * 0.70710678118654752f));
}
__device__ __forceinline__ void split_bf16(float v, uint16_t& h, uint16_t& l) {
    __nv_bfloat16 hb = __float2bfloat16(v);
    float rem = v - __bfloat162float(hb);
    h = __bfloat16_as_ushort(hb);
    l = __bfloat16_as_ushort(__float2bfloat16(rem));
}
// pack (g0,g1) -> hi-bf16x2 and residual lo-bf16x2 in ~6 ops
__device__ __forceinline__ void pack_split(float g0, float g1,
                                           uint32_t& hpk, uint32_t& lpk) {
    asm("cvt.rn.bf16x2.f32 %0, %1, %2;" : "=r"(hpk) : "f"(g1), "f"(g0));
    float h0f = __uint_as_float(hpk << 16);
    float h1f = __uint_as_float(hpk & 0xffff0000u);
    asm("cvt.rn.bf16x2.f32 %0, %1, %2;" : "=r"(lpk) : "f"(g1 - h1f), "f"(g0 - h0f));
}
__device__ __forceinline__ void ldm_x4(uint32_t* r, uint32_t addr) {
    asm volatile("ldmatrix.sync.aligned.m8n8.x4.shared.b16 {%0,%1,%2,%3}, [%4];"
                 : "=r"(r[0]), "=r"(r[1]), "=r"(r[2]), "=r"(r[3]) : "r"(addr));
}
__device__ __forceinline__ void ldm_x2(uint32_t& b0, uint32_t& b1, uint32_t addr) {
    asm volatile("ldmatrix.sync.aligned.m8n8.x2.shared.b16 {%0,%1}, [%2];"
                 : "=r"(b0), "=r"(b1) : "r"(addr));
}
__device__ __forceinline__ void mma16816(float& c0, float& c1, float& c2, float& c3,
                                         const uint32_t* a, uint32_t b0, uint32_t b1) {
    asm volatile(
        "mma.sync.aligned.m16n8k16.row.col.f32.bf16.bf16.f32 "
        "{%0,%1,%2,%3},{%4,%5,%6,%7},{%8,%9},{%0,%1,%2,%3};"
        : "+f"(c0), "+f"(c1), "+f"(c2), "+f"(c3)
        : "r"(a[0]), "r"(a[1]), "r"(a[2]), "r"(a[3]), "r"(b0), "r"(b1));
}

// ---------------- kernel 1: im2col + split ----------------
__global__ void __launch_bounds__(256)
im2col_kernel(const float* __restrict__ x) {
    int idx = blockIdx.x * 256 + threadIdx.x;
    if (idx >= MTOT * 64) return;
    int m = idx >> 6, c64 = idx & 63;
    float v = 0.0f;
    if (c64 < 60) {
        int c = c64 / 15, j = c64 - c * 15;
        int b = m / NOUT, p = m - b * NOUT;
        v = x[b * (4 * LSEQ) + c * LSEQ + p + j];
    }
    uint16_t h, l;
    split_bf16(v, h, l);
    g_imh[idx] = __ushort_as_bfloat16(h);
    g_iml[idx] = __ushort_as_bfloat16(l);
}

// ---------------- kernel 2 ----------------
__device__ __forceinline__ void stage_w(char* sm, const float* w,
                                        int Ktrue, int Ntrue, int Npad, int KW,
                                        int wo, int tid) {
    __nv_bfloat16* wh = reinterpret_cast<__nv_bfloat16*>(sm + SM_WHI) + wo;
    __nv_bfloat16* wl = reinterpret_cast<__nv_bfloat16*>(sm + SM_WLO) + wo;
    int n = Npad * KW;
    for (int i = tid; i < n; i += NTH) {
        int nn = i / KW, kk = i - nn * KW;
        float v = (nn < Ntrue && kk < Ktrue) ? w[kk * Ntrue + nn] : 0.0f;
        uint16_t h, l;
        split_bf16(v, h, l);
        wh[i] = __ushort_as_bfloat16(h);
        wl[i] = __ushort_as_bfloat16(l);
    }
}

// One layer, dual accumulator chains d / e.
template<int KS, int NT, int KW, bool LAST>
__device__ __forceinline__ void do_layer(const uint32_t ah[][4], const uint32_t al[][4],
                                         uint32_t anh[][4], uint32_t anl[][4],
                                         uint32_t whb, uint32_t wlb,
                                         const float* __restrict__ bias,
                                         const float* __restrict__ hw,
                                         int lane, float& p0, float& p1) {
    const uint32_t brow4 = (uint32_t)(lane & 7) * (KW * 2) + (uint32_t)(lane >> 3) * 16;
    const int col = 2 * (lane & 3);

    #pragma unroll
    for (int n = 0; n < NT; ++n) {
        float d0 = 0.f, d1 = 0.f, d2 = 0.f, d3 = 0.f;
        float e0 = 0.f, e1 = 0.f, e2 = 0.f, e3 = 0.f;
        const uint32_t bh = whb + (uint32_t)(n * 8) * (KW * 2) + brow4;
        const uint32_t bl = wlb + (uint32_t)(n * 8) * (KW * 2) + brow4;

        // hi-B pass: Ah->d, Al->e (shared B regs, independent chains)
        #pragma unroll
        for (int p = 0; p < KS / 2; ++p) {
            uint32_t b[4];
            ldm_x4(b, bh + p * 64);
            mma16816(d0, d1, d2, d3, ah[2*p],     b[0], b[1]);
            mma16816(e0, e1, e2, e3, al[2*p],     b[0], b[1]);
            mma16816(d0, d1, d2, d3, ah[2*p + 1], b[2], b[3]);
            mma16816(e0, e1, e2, e3, al[2*p + 1], b[2], b[3]);
        }
        if (KS & 1) {
            uint32_t b0, b1;
            ldm_x2(b0, b1, bh + (KS - 1) * 32);
            mma16816(d0, d1, d2, d3, ah[KS - 1], b0, b1);
            mma16816(e0, e1, e2, e3, al[KS - 1], b0, b1);
        }
        // lo-B pass: Ah only, alternate chains
        #pragma unroll
        for (int p = 0; p < KS / 2; ++p) {
            uint32_t b[4];
            ldm_x4(b, bl + p * 64);
            mma16816(d0, d1, d2, d3, ah[2*p],     b[0], b[1]);
            mma16816(e0, e1, e2, e3, ah[2*p + 1], b[2], b[3]);
        }
        if (KS & 1) {
            uint32_t b0, b1;
            ldm_x2(b0, b1, bl + (KS - 1) * 32);
            mma16816(e0, e1, e2, e3, ah[KS - 1], b0, b1);
        }

        const int cg = n * 8 + col;
        const float bb0 = bias[cg], bb1 = bias[cg + 1];
        const float g0 = gelu_exact(d0 + e0 + bb0);
        const float g1 = gelu_exact(d1 + e1 + bb1);
        const float g2 = gelu_exact(d2 + e2 + bb0);
        const float g3 = gelu_exact(d3 + e3 + bb1);

        if (!LAST) {
            pack_split(g0, g1, anh[n / 2][(n & 1) * 2 + 0], anl[n / 2][(n & 1) * 2 + 0]);
            pack_split(g2, g3, anh[n / 2][(n & 1) * 2 + 1], anl[n / 2][(n & 1) * 2 + 1]);
        } else {
            p0 = fmaf(g0, hw[cg], fmaf(g1, hw[cg + 1], p0));
            p1 = fmaf(g2, hw[cg], fmaf(g3, hw[cg + 1], p1));
        }
    }
}

__global__ void __launch_bounds__(NTH, 1)
expert_kernel(const float* __restrict__ w0, const float* __restrict__ b0,
              const float* __restrict__ w1, const float* __restrict__ b1,
              const float* __restrict__ w2, const float* __restrict__ b2,
              const float* __restrict__ w3, const float* __restrict__ b3,
              const float* __restrict__ w4, const float* __restrict__ b4,
              const float* __restrict__ head_w, const float* __restrict__ head_b,
              float* __restrict__ out) {
    extern __shared__ char sm[];
    const uint32_t sb = smem_u32(sm);
    const int k = blockIdx.x;
    const int grp = blockIdx.y;
    const int tid = threadIdx.x;
    const int lane = tid & 31;
    const int wid = tid >> 5;

    {
        float* bm = reinterpret_cast<float*>(sm + SM_BIAS);
        const float* bs[5] = {b0, b1, b2, b3, b4};
        const int ntrue[5] = {72, 86, 86, 71, 59};
        const int npad[5] = {80, 96, 96, 80, 64};
        const int boff[5] = {0, 80, 176, 272, 352};
        #pragma unroll
        for (int L = 0; L < 5; ++L) {
            const float* src = bs[L] + k * ntrue[L];
            for (int i = tid; i < npad[L]; i += NTH)
                bm[boff[L] + i] = (i < ntrue[L]) ? src[i] : 0.0f;
        }
        float* hwm = reinterpret_cast<float*>(sm + SM_HW);
        for (int i = tid; i < 64; i += NTH)
            hwm[i] = (i < 59) ? head_w[i] : 0.0f;
    }
    stage_w(sm, w0 + k * 60 * 72, 60, 72, 80,  72, WO0, tid);
    stage_w(sm, w1 + k * 72 * 86, 72, 86, 96,  88, WO1, tid);
    stage_w(sm, w2 + k * 86 * 86, 86, 86, 96, 104, WO2, tid);
    stage_w(sm, w3 + k * 86 * 71, 86, 71, 80, 104, WO3, tid);
    stage_w(sm, w4 + k * 71 * 59, 71, 59, 64,  88, WO4, tid);
    __syncthreads();

    const float hb = head_b[0];
    const float* bm = reinterpret_cast<const float*>(sm + SM_BIAS);
    const float* hwm = reinterpret_cast<const float*>(sm + SM_HW);
    const int g = lane >> 2;
    const int col0 = 2 * (lane & 3);

    uint32_t A0h[6][4], A0l[6][4], A1h[6][4], A1l[6][4];

    for (int tt = wid; tt < TPG; tt += NWARP) {
        const int tile = grp * TPG + tt;
        if (tile >= NTILE) continue;
        const int m0 = tile * 16;

        {
            const char* h0p = (const char*)(g_imh + (m0 + g) * 64 + col0);
            const char* h8p = (const char*)(g_imh + (m0 + g + 8) * 64 + col0);
            const char* l0p = (const char*)(g_iml + (m0 + g) * 64 + col0);
            const char* l8p = (const char*)(g_iml + (m0 + g + 8) * 64 + col0);
            #pragma unroll
            for (int j = 0; j < 4; ++j) {
                A0h[j][0] = *(const uint32_t*)(h0p + j * 32);
                A0h[j][1] = *(const uint32_t*)(h8p + j * 32);
                A0h[j][2] = *(const uint32_t*)(h0p + j * 32 + 16);
                A0h[j][3] = *(const uint32_t*)(h8p + j * 32 + 16);
                A0l[j][0] = *(const uint32_t*)(l0p + j * 32);
                A0l[j][1] = *(const uint32_t*)(l8p + j * 32);
                A0l[j][2] = *(const uint32_t*)(l0p + j * 32 + 16);
                A0l[j][3] = *(const uint32_t*)(l8p + j * 32 + 16);
            }
        }

        float p0 = 0.0f, p1 = 0.0f;
        do_layer<4, 10,  72, false>(A0h, A0l, A1h, A1l,
            sb + SM_WHI + WO0 * 2, sb + SM_WLO + WO0 * 2, bm + 0,   hwm, lane, p0, p1);
        do_layer<5, 12,  88, false>(A1h, A1l, A0h, A0l,
            sb + SM_WHI + WO1 * 2, sb + SM_WLO + WO1 * 2, bm + 80,  hwm, lane, p0, p1);
        do_layer<6, 12, 104, false>(A0h, A0l, A1h, A1l,
            sb + SM_WHI + WO2 * 2, sb + SM_WLO + WO2 * 2, bm + 176, hwm, lane, p0, p1);
        do_layer<6, 10, 104, false>(A1h, A1l, A0h, A0l,
            sb + SM_WHI + WO3 * 2, sb + SM_WLO + WO3 * 2, bm + 272, hwm, lane, p0, p1);
        do_layer<5,  8,  88, true >(A0h, A0l, A1h, A1l,
            sb + SM_WHI + WO4 * 2, sb + SM_WLO + WO4 * 2, bm + 352, hwm, lane, p0, p1);

        p0 += __shfl_xor_sync(0xffffffffu, p0, 1);
        p0 += __shfl_xor_sync(0xffffffffu, p0, 2);
        p1 += __shfl_xor_sync(0xffffffffu, p1, 1);
        p1 += __shfl_xor_sync(0xffffffffu, p1, 2);
        if ((lane & 3) == 0) {
            int m = m0 + g;
            int b = m / NOUT, p = m - b * NOUT;
            out[(b * NK + k) * NOUT + p] = p0 + hb;
            m += 8;
            b = m / NOUT; p = m - b * NOUT;
            out[(b * NK + k) * NOUT + p] = p1 + hb;
        }
    }
}

extern "C" void kernel_launch(void* const* d_in, const int* in_sizes, int n_in,
                              void* d_out, int out_size) {
    const float* x      = (const float*)d_in[0];
    const float* w0     = (const float*)d_in[1];
    const float* b0     = (const float*)d_in[2];
    const float* w1     = (const float*)d_in[3];
    const float* b1     = (const float*)d_in[4];
    const float* w2     = (const float*)d_in[5];
    const float* b2     = (const float*)d_in[6];
    const float* w3     = (const float*)d_in[7];
    const float* b3     = (const float*)d_in[8];
    const float* w4     = (const float*)d_in[9];
    const float* b4     = (const float*)d_in[10];
    const float* head_w = (const float*)d_in[11];
    const float* head_b = (const float*)d_in[12];
    float* out = (float*)d_out;

    im2col_kernel<<<(MTOT * 64 + 255) / 256, 256>>>(x);

    cudaFuncSetAttribute(expert_kernel,
                         cudaFuncAttributeMaxDynamicSharedMemorySize, SMEM_TOTAL);
    dim3 grid(NK, NGRP);
    expert_kernel<<<grid, NTH, SMEM_TOTAL>>>(
        w0, b0, w1, b1, w2, b2, w3, b3, w4, b4, head_w, head_b, out);
}

// round 11
// speedup vs baseline: 1.4783x; 1.3738x over previous
#include <cuda_runtime.h>
#include <cuda_fp16.h>
#include <math.h>
#include <stdint.h>

// conv_nonlinear R10: fp16 precision re-budget.
// A = single fp16 (trunc err 2^-12), B = fp16 hi+lo (exact to 24 bits).
// 2 MMA passes: D = A*Bh + A*Bl, fp32 accum. Predicted rel_err ~3e-4 (<1e-3).
// vs R7: -33% HMMA, -50% A regs (no lo plane), 1-op epilogue pack ->
// 512 thr / 16 warps (4/SMSP), grid 64x7 = 448 CTAs (~3.03 waves).
// Activations register-resident (C-fragment == next A-fragment identity).

#define NB 16
#define NK 64
#define LSEQ 1000
#define NOUT 986
#define MTOT (NB*NOUT)     // 15776
#define NTILE (MTOT/16)    // 986
#define NTH 512
#define NWARP 16
#define NGRP 7
#define TPG 141            // 7*141 = 987 >= 986

// Ktrue {60,72,86,86,71}  Ntrue {72,86,86,71,59}
// KSTEPS {4,5,6,6,5}  NT=Npad/8 {10,12,12,10,8}
// KW (weight row stride, elems; KW/8 odd -> conflict-free ldmatrix) {72,88,104,104,88}
#define WO0 0
#define WO1 5760
#define WO2 14208
#define WO3 24192
#define WO4 32512
#define WTOTAL 38144

#define SM_WHI  0
#define SM_WLO  (WTOTAL*2)          // 76288
#define SM_BIAS (WTOTAL*4)          // 152576
#define SM_HW   (SM_BIAS + 416*4)   // 154240
#define SMEM_TOTAL (SM_HW + 64*4)   // 154496

// im2col scratch: [MTOT][64] fp16 (single plane)
__device__ __half g_imh[MTOT * 64];

__device__ __forceinline__ uint32_t smem_u32(const void* p) {
    uint32_t a;
    asm("{ .reg .u64 t; cvta.to.shared.u64 t, %1; cvt.u32.u64 %0, t; }"
        : "=r"(a) : "l"(p));
    return a;
}
__device__ __forceinline__ float gelu_exact(float v) {
    return 0.5f * v * (1.0f + erff(v * 0.70710678118654752f));
}
// pack (g0,g1) -> fp16x2, g0 in low half
__device__ __forceinline__ uint32_t pack_f16(float g0, float g1) {
    uint32_t r;
    asm("cvt.rn.f16x2.f32 %0, %1, %2;" : "=r"(r) : "f"(g1), "f"(g0));
    return r;
}
__device__ __forceinline__ void ldm_x4(uint32_t* r, uint32_t addr) {
    asm volatile("ldmatrix.sync.aligned.m8n8.x4.shared.b16 {%0,%1,%2,%3}, [%4];"
                 : "=r"(r[0]), "=r"(r[1]), "=r"(r[2]), "=r"(r[3]) : "r"(addr));
}
__device__ __forceinline__ void ldm_x2(uint32_t& b0, uint32_t& b1, uint32_t addr) {
    asm volatile("ldmatrix.sync.aligned.m8n8.x2.shared.b16 {%0,%1}, [%2];"
                 : "=r"(b0), "=r"(b1) : "r"(addr));
}
__device__ __forceinline__ void mma16816(float& c0, float& c1, float& c2, float& c3,
                                         const uint32_t* a, uint32_t b0, uint32_t b1) {
    asm volatile(
        "mma.sync.aligned.m16n8k16.row.col.f32.f16.f16.f32 "
        "{%0,%1,%2,%3},{%4,%5,%6,%7},{%8,%9},{%0,%1,%2,%3};"
        : "+f"(c0), "+f"(c1), "+f"(c2), "+f"(c3)
        : "r"(a[0]), "r"(a[1]), "r"(a[2]), "r"(a[3]), "r"(b0), "r"(b1));
}

// ---------------- kernel 1: im2col (single fp16 plane) ----------------
__global__ void __launch_bounds__(256)
im2col_kernel(const float* __restrict__ x) {
    int idx = blockIdx.x * 256 + threadIdx.x;
    if (idx >= MTOT * 64) return;
    int m = idx >> 6, c64 = idx & 63;
    float v = 0.0f;
    if (c64 < 60) {
        int c = c64 / 15, j = c64 - c * 15;
        int b = m / NOUT, p = m - b * NOUT;
        v = x[b * (4 * LSEQ) + c * LSEQ + p + j];
    }
    g_imh[idx] = __float2half_rn(v);
}

// ---------------- kernel 2 ----------------
__device__ __forceinline__ void stage_w(char* sm, const float* w,
                                        int Ktrue, int Ntrue, int Npad, int KW,
                                        int wo, int tid) {
    __half* wh = reinterpret_cast<__half*>(sm + SM_WHI) + wo;
    __half* wl = reinterpret_cast<__half*>(sm + SM_WLO) + wo;
    int n = Npad * KW;
    for (int i = tid; i < n; i += NTH) {
        int nn = i / KW, kk = i - nn * KW;
        float v = (nn < Ntrue && kk < Ktrue) ? w[kk * Ntrue + nn] : 0.0f;
        __half h = __float2half_rn(v);
        wh[i] = h;
        wl[i] = __float2half_rn(v - __half2float(h));
    }
}

// One layer: A (regs, fp16) x B (smem, fp16 hi/lo) -> gelu -> next A or head.
template<int KS, int NT, int KW, bool LAST>
__device__ __forceinline__ void do_layer(const uint32_t a[][4], uint32_t an[][4],
                                         uint32_t whb, uint32_t wlb,
                                         const float* __restrict__ bias,
                                         const float* __restrict__ hw,
                                         int lane, float& p0, float& p1) {
    const uint32_t brow4 = (uint32_t)(lane & 7) * (KW * 2) + (uint32_t)(lane >> 3) * 16;
    const int col = 2 * (lane & 3);

    #pragma unroll
    for (int n = 0; n < NT; ++n) {
        float c0 = 0.f, c1 = 0.f, c2 = 0.f, c3 = 0.f;
        const uint32_t bh = whb + (uint32_t)(n * 8) * (KW * 2) + brow4;
        const uint32_t bl = wlb + (uint32_t)(n * 8) * (KW * 2) + brow4;

        // pass 1: A * Bh
        #pragma unroll
        for (int p = 0; p < KS / 2; ++p) {
            uint32_t b[4];
            ldm_x4(b, bh + p * 64);
            mma16816(c0, c1, c2, c3, a[2*p],     b[0], b[1]);
            mma16816(c0, c1, c2, c3, a[2*p + 1], b[2], b[3]);
        }
        if (KS & 1) {
            uint32_t b0, b1;
            ldm_x2(b0, b1, bh + (KS - 1) * 32);
            mma16816(c0, c1, c2, c3, a[KS - 1], b0, b1);
        }
        // pass 2: A * Bl
        #pragma unroll
        for (int p = 0; p < KS / 2; ++p) {
            uint32_t b[4];
            ldm_x4(b, bl + p * 64);
            mma16816(c0, c1, c2, c3, a[2*p],     b[0], b[1]);
            mma16816(c0, c1, c2, c3, a[2*p + 1], b[2], b[3]);
        }
        if (KS & 1) {
            uint32_t b0, b1;
            ldm_x2(b0, b1, bl + (KS - 1) * 32);
            mma16816(c0, c1, c2, c3, a[KS - 1], b0, b1);
        }

        const int cg = n * 8 + col;
        const float bb0 = bias[cg], bb1 = bias[cg + 1];
        const float g0 = gelu_exact(c0 + bb0);
        const float g1 = gelu_exact(c1 + bb1);
        const float g2 = gelu_exact(c2 + bb0);
        const float g3 = gelu_exact(c3 + bb1);

        if (!LAST) {
            // C(n-tile) -> A fragment (k-chunk n/2, regs (n&1)*2, +1)
            an[n / 2][(n & 1) * 2 + 0] = pack_f16(g0, g1);
            an[n / 2][(n & 1) * 2 + 1] = pack_f16(g2, g3);
        } else {
            p0 = fmaf(g0, hw[cg], fmaf(g1, hw[cg + 1], p0));
            p1 = fmaf(g2, hw[cg], fmaf(g3, hw[cg + 1], p1));
        }
    }
}

__global__ void __launch_bounds__(NTH, 1)
expert_kernel(const float* __restrict__ w0, const float* __restrict__ b0,
              const float* __restrict__ w1, const float* __restrict__ b1,
              const float* __restrict__ w2, const float* __restrict__ b2,
              const float* __restrict__ w3, const float* __restrict__ b3,
              const float* __restrict__ w4, const float* __restrict__ b4,
              const float* __restrict__ head_w, const float* __restrict__ head_b,
              float* __restrict__ out) {
    extern __shared__ char sm[];
    const uint32_t sb = smem_u32(sm);
    const int k = blockIdx.x;
    const int grp = blockIdx.y;
    const int tid = threadIdx.x;
    const int lane = tid & 31;
    const int wid = tid >> 5;

    {
        float* bm = reinterpret_cast<float*>(sm + SM_BIAS);
        const float* bs[5] = {b0, b1, b2, b3, b4};
        const int ntrue[5] = {72, 86, 86, 71, 59};
        const int npad[5] = {80, 96, 96, 80, 64};
        const int boff[5] = {0, 80, 176, 272, 352};
        #pragma unroll
        for (int L = 0; L < 5; ++L) {
            const float* src = bs[L] + k * ntrue[L];
            for (int i = tid; i < npad[L]; i += NTH)
                bm[boff[L] + i] = (i < ntrue[L]) ? src[i] : 0.0f;
        }
        float* hwm = reinterpret_cast<float*>(sm + SM_HW);
        for (int i = tid; i < 64; i += NTH)
            hwm[i] = (i < 59) ? head_w[i] : 0.0f;
    }
    stage_w(sm, w0 + k * 60 * 72, 60, 72, 80,  72, WO0, tid);
    stage_w(sm, w1 + k * 72 * 86, 72, 86, 96,  88, WO1, tid);
    stage_w(sm, w2 + k * 86 * 86, 86, 86, 96, 104, WO2, tid);
    stage_w(sm, w3 + k * 86 * 71, 86, 71, 80, 104, WO3, tid);
    stage_w(sm, w4 + k * 71 * 59, 71, 59, 64,  88, WO4, tid);
    __syncthreads();

    const float hb = head_b[0];
    const float* bm = reinterpret_cast<const float*>(sm + SM_BIAS);
    const float* hwm = reinterpret_cast<const float*>(sm + SM_HW);
    const int g = lane >> 2;
    const int col0 = 2 * (lane & 3);

    uint32_t A0[6][4], A1[6][4];

    for (int tt = wid; tt < TPG; tt += NWARP) {
        const int tile = grp * TPG + tt;
        if (tile >= NTILE) continue;
        const int m0 = tile * 16;

        // layer-0 A fragments straight from precomputed im2col
        {
            const char* h0p = (const char*)(g_imh + (m0 + g) * 64 + col0);
            const char* h8p = (const char*)(g_imh + (m0 + g + 8) * 64 + col0);
            #pragma unroll
            for (int j = 0; j < 4; ++j) {
                A0[j][0] = *(const uint32_t*)(h0p + j * 32);
                A0[j][1] = *(const uint32_t*)(h8p + j * 32);
                A0[j][2] = *(const uint32_t*)(h0p + j * 32 + 16);
                A0[j][3] = *(const uint32_t*)(h8p + j * 32 + 16);
            }
        }

        float p0 = 0.0f, p1 = 0.0f;
        do_layer<4, 10,  72, false>(A0, A1,
            sb + SM_WHI + WO0 * 2, sb + SM_WLO + WO0 * 2, bm + 0,   hwm, lane, p0, p1);
        do_layer<5, 12,  88, false>(A1, A0,
            sb + SM_WHI + WO1 * 2, sb + SM_WLO + WO1 * 2, bm + 80,  hwm, lane, p0, p1);
        do_layer<6, 12, 104, false>(A0, A1,
            sb + SM_WHI + WO2 * 2, sb + SM_WLO + WO2 * 2, bm + 176, hwm, lane, p0, p1);
        do_layer<6, 10, 104, false>(A1, A0,
            sb + SM_WHI + WO3 * 2, sb + SM_WLO + WO3 * 2, bm + 272, hwm, lane, p0, p1);
        do_layer<5,  8,  88, true >(A0, A1,
            sb + SM_WHI + WO4 * 2, sb + SM_WLO + WO4 * 2, bm + 352, hwm, lane, p0, p1);

        // head reduce: lanes {4g..4g+3} hold cols of rows g and g+8
        p0 += __shfl_xor_sync(0xffffffffu, p0, 1);
        p0 += __shfl_xor_sync(0xffffffffu, p0, 2);
        p1 += __shfl_xor_sync(0xffffffffu, p1, 1);
        p1 += __shfl_xor_sync(0xffffffffu, p1, 2);
        if ((lane & 3) == 0) {
            int m = m0 + g;
            int b = m / NOUT, p = m - b * NOUT;
            out[(b * NK + k) * NOUT + p] = p0 + hb;
            m += 8;
            b = m / NOUT; p = m - b * NOUT;
            out[(b * NK + k) * NOUT + p] = p1 + hb;
        }
    }
}

extern "C" void kernel_launch(void* const* d_in, const int* in_sizes, int n_in,
                              void* d_out, int out_size) {
    const float* x      = (const float*)d_in[0];
    const float* w0     = (const float*)d_in[1];
    const float* b0     = (const float*)d_in[2];
    const float* w1     = (const float*)d_in[3];
    const float* b1     = (const float*)d_in[4];
    const float* w2     = (const float*)d_in[5];
    const float* b2     = (const float*)d_in[6];
    const float* w3     = (const float*)d_in[7];
    const float* b3     = (const float*)d_in[8];
    const float* w4     = (const float*)d_in[9];
    const float* b4     = (const float*)d_in[10];
    const float* head_w = (const float*)d_in[11];
    const float* head_b = (const float*)d_in[12];
    float* out = (float*)d_out;

    im2col_kernel<<<(MTOT * 64 + 255) / 256, 256>>>(x);

    cudaFuncSetAttribute(expert_kernel,
                         cudaFuncAttributeMaxDynamicSharedMemorySize, SMEM_TOTAL);
    dim3 grid(NK, NGRP);
    expert_kernel<<<grid, NTH, SMEM_TOTAL>>>(
        w0, b0, w1, b1, w2, b2, w3, b3, w4, b4, head_w, head_b, out);
}

// round 15
// speedup vs baseline: 1.8843x; 1.2746x over previous
#include <cuda_runtime.h>
#include <cuda_fp16.h>
#include <math.h>
#include <stdint.h>

// conv_nonlinear R11: R10 (fp16 A single-plane, B hi/lo 2-pass, 512thr) +
// (1) custom branch-free packed-f32x2 GELU (A&S 7.1.26 erf, |eps|<=1.5e-7)
//     replacing erff: ~26 ops/pair vs ~45, bias add packed;
// (2) skip full-padding n-tiles in layers 0-3 (MMA + epilogue), zero-fill
//     the corresponding next-layer A fragments.
// gelu(v) = 0.5(v+|v|) - 0.5|v|*P(t)*exp(-v^2/2), t=1/(1+p*|v|/sqrt2).

#define NB 16
#define NK 64
#define LSEQ 1000
#define NOUT 986
#define MTOT (NB*NOUT)     // 15776
#define NTILE (MTOT/16)    // 986
#define NTH 512
#define NWARP 16
#define NGRP 7
#define TPG 141            // 7*141 = 987 >= 986

#define WO0 0
#define WO1 5760
#define WO2 14208
#define WO3 24192
#define WO4 32512
#define WTOTAL 38144

#define SM_WHI  0
#define SM_WLO  (WTOTAL*2)          // 76288
#define SM_BIAS (WTOTAL*4)          // 152576
#define SM_HW   (SM_BIAS + 416*4)   // 154240
#define SMEM_TOTAL (SM_HW + 64*4)   // 154496

__device__ __half g_imh[MTOT * 64];

typedef unsigned long long u64;

__device__ __forceinline__ uint32_t smem_u32(const void* p) {
    uint32_t a;
    asm("{ .reg .u64 t; cvta.to.shared.u64 t, %1; cvt.u32.u64 %0, t; }"
        : "=r"(a) : "l"(p));
    return a;
}
__device__ __forceinline__ u64 pk2(float a, float b) {
    u64 r; asm("mov.b64 %0, {%1, %2};" : "=l"(r) : "f"(a), "f"(b)); return r;
}
__device__ __forceinline__ void upk2(u64 p, float& a, float& b) {
    asm("mov.b64 {%0, %1}, %2;" : "=f"(a), "=f"(b) : "l"(p));
}
__device__ __forceinline__ u64 mul2(u64 a, u64 b) {
    u64 r; asm("mul.rn.f32x2 %0, %1, %2;" : "=l"(r) : "l"(a), "l"(b)); return r;
}
__device__ __forceinline__ u64 add2(u64 a, u64 b) {
    u64 r; asm("add.rn.f32x2 %0, %1, %2;" : "=l"(r) : "l"(a), "l"(b)); return r;
}
__device__ __forceinline__ u64 fma2_(u64 a, u64 b, u64 c) {
    u64 r; asm("fma.rn.f32x2 %0, %1, %2, %3;" : "=l"(r) : "l"(a), "l"(b), "l"(c)); return r;
}
__device__ __forceinline__ float ex2f(float x) {
    float r; asm("ex2.approx.f32 %0, %1;" : "=f"(r) : "f"(x)); return r;
}
__device__ __forceinline__ float rcpf(float x) {
    float r; asm("rcp.approx.f32 %0, %1;" : "=f"(r) : "f"(x)); return r;
}

// exact-GELU on a packed f32 pair, branch-free (A&S 7.1.26, abs err < 2e-6)
__device__ __forceinline__ u64 gelu2(u64 V) {
    const u64 PP   = pk2((float)(0.3275911 * 0.7071067811865475),
                         (float)(0.3275911 * 0.7071067811865475));
    const u64 ONE2 = pk2(1.0f, 1.0f);
    const u64 A5   = pk2(1.061405429f, 1.061405429f);
    const u64 A4   = pk2(-1.453152027f, -1.453152027f);
    const u64 A3   = pk2(1.421413741f, 1.421413741f);
    const u64 A2   = pk2(-0.284496736f, -0.284496736f);
    const u64 A1   = pk2(0.254829592f, 0.254829592f);
    const u64 NHL2 = pk2(-0.7213475204444817f, -0.7213475204444817f);
    const u64 HALF = pk2(0.5f, 0.5f);
    const u64 MHALF= pk2(-0.5f, -0.5f);

    u64 AV = V & 0x7FFFFFFF7FFFFFFFull;
    u64 W  = mul2(V, V);
    u64 Wl = mul2(W, NHL2);
    float w0, w1; upk2(Wl, w0, w1);
    u64 E  = pk2(ex2f(w0), ex2f(w1));          // exp(-v^2/2)
    u64 Td = fma2_(AV, PP, ONE2);
    float t0, t1; upk2(Td, t0, t1);
    u64 T  = pk2(rcpf(t0), rcpf(t1));
    u64 P  = fma2_(T, A5, A4);
    P = fma2_(P, T, A3);
    P = fma2_(P, T, A2);
    P = fma2_(P, T, A1);
    P = mul2(P, T);
    u64 PE = mul2(P, E);
    u64 Q  = mul2(mul2(AV, PE), MHALF);        // -0.5|v|Pe
    u64 H  = add2(V, AV);                      // v + |v|
    return fma2_(H, HALF, Q);                  // 0.5(v+|v|) - 0.5|v|Pe
}

// pack (g0,g1) -> fp16x2, g0 in low half
__device__ __forceinline__ uint32_t pack_f16(float g0, float g1) {
    uint32_t r;
    asm("cvt.rn.f16x2.f32 %0, %1, %2;" : "=r"(r) : "f"(g1), "f"(g0));
    return r;
}
__device__ __forceinline__ void ldm_x4(uint32_t* r, uint32_t addr) {
    asm volatile("ldmatrix.sync.aligned.m8n8.x4.shared.b16 {%0,%1,%2,%3}, [%4];"
                 : "=r"(r[0]), "=r"(r[1]), "=r"(r[2]), "=r"(r[3]) : "r"(addr));
}
__device__ __forceinline__ void ldm_x2(uint32_t& b0, uint32_t& b1, uint32_t addr) {
    asm volatile("ldmatrix.sync.aligned.m8n8.x2.shared.b16 {%0,%1}, [%2];"
                 : "=r"(b0), "=r"(b1) : "r"(addr));
}
__device__ __forceinline__ void mma16816(float& c0, float& c1, float& c2, float& c3,
                                         const uint32_t* a, uint32_t b0, uint32_t b1) {
    asm volatile(
        "mma.sync.aligned.m16n8k16.row.col.f32.f16.f16.f32 "
        "{%0,%1,%2,%3},{%4,%5,%6,%7},{%8,%9},{%0,%1,%2,%3};"
        : "+f"(c0), "+f"(c1), "+f"(c2), "+f"(c3)
        : "r"(a[0]), "r"(a[1]), "r"(a[2]), "r"(a[3]), "r"(b0), "r"(b1));
}

// ---------------- kernel 1: im2col (single fp16 plane) ----------------
__global__ void __launch_bounds__(256)
im2col_kernel(const float* __restrict__ x) {
    int idx = blockIdx.x * 256 + threadIdx.x;
    if (idx >= MTOT * 64) return;
    int m = idx >> 6, c64 = idx & 63;
    float v = 0.0f;
    if (c64 < 60) {
        int c = c64 / 15, j = c64 - c * 15;
        int b = m / NOUT, p = m - b * NOUT;
        v = x[b * (4 * LSEQ) + c * LSEQ + p + j];
    }
    g_imh[idx] = __float2half_rn(v);
}

// ---------------- kernel 2 ----------------
__device__ __forceinline__ void stage_w(char* sm, const float* w,
                                        int Ktrue, int Ntrue, int Npad, int KW,
                                        int wo, int tid) {
    __half* wh = reinterpret_cast<__half*>(sm + SM_WHI) + wo;
    __half* wl = reinterpret_cast<__half*>(sm + SM_WLO) + wo;
    int n = Npad * KW;
    for (int i = tid; i < n; i += NTH) {
        int nn = i / KW, kk = i - nn * KW;
        float v = (nn < Ntrue && kk < Ktrue) ? w[kk * Ntrue + nn] : 0.0f;
        __half h = __float2half_rn(v);
        wh[i] = h;
        wl[i] = __float2half_rn(v - __half2float(h));
    }
}

// One layer. NTC = compute n-tiles (full-pad tiles skipped, A frags zeroed).
template<int KS, int NT, int NTC, int KW, bool LAST>
__device__ __forceinline__ void do_layer(const uint32_t a[][4], uint32_t an[][4],
                                         uint32_t whb, uint32_t wlb,
                                         const float* __restrict__ bias,
                                         const float* __restrict__ hw,
                                         int lane, float& p0, float& p1) {
    const uint32_t brow4 = (uint32_t)(lane & 7) * (KW * 2) + (uint32_t)(lane >> 3) * 16;
    const int col = 2 * (lane & 3);

    #pragma unroll
    for (int n = 0; n < NTC; ++n) {
        float c0 = 0.f, c1 = 0.f, c2 = 0.f, c3 = 0.f;
        const uint32_t bh = whb + (uint32_t)(n * 8) * (KW * 2) + brow4;
        const uint32_t bl = wlb + (uint32_t)(n * 8) * (KW * 2) + brow4;

        // pass 1: A * Bh
        #pragma unroll
        for (int p = 0; p < KS / 2; ++p) {
            uint32_t b[4];
            ldm_x4(b, bh + p * 64);
            mma16816(c0, c1, c2, c3, a[2*p],     b[0], b[1]);
            mma16816(c0, c1, c2, c3, a[2*p + 1], b[2], b[3]);
        }
        if (KS & 1) {
            uint32_t b0, b1;
            ldm_x2(b0, b1, bh + (KS - 1) * 32);
            mma16816(c0, c1, c2, c3, a[KS - 1], b0, b1);
        }
        // pass 2: A * Bl
        #pragma unroll
        for (int p = 0; p < KS / 2; ++p) {
            uint32_t b[4];
            ldm_x4(b, bl + p * 64);
            mma16816(c0, c1, c2, c3, a[2*p],     b[0], b[1]);
            mma16816(c0, c1, c2, c3, a[2*p + 1], b[2], b[3]);
        }
        if (KS & 1) {
            uint32_t b0, b1;
            ldm_x2(b0, b1, bl + (KS - 1) * 32);
            mma16816(c0, c1, c2, c3, a[KS - 1], b0, b1);
        }

        const int cg = n * 8 + col;
        const u64 B2 = *reinterpret_cast<const u64*>(bias + cg);  // 8B aligned
        const u64 G01 = gelu2(add2(pk2(c0, c1), B2));
        const u64 G23 = gelu2(add2(pk2(c2, c3), B2));
        float g0, g1, g2, g3;
        upk2(G01, g0, g1);
        upk2(G23, g2, g3);

        if (!LAST) {
            an[n / 2][(n & 1) * 2 + 0] = pack_f16(g0, g1);
            an[n / 2][(n & 1) * 2 + 1] = pack_f16(g2, g3);
        } else {
            p0 = fmaf(g0, hw[cg], fmaf(g1, hw[cg + 1], p0));
            p1 = fmaf(g2, hw[cg], fmaf(g3, hw[cg + 1], p1));
        }
    }
    if (!LAST && NTC < NT) {   // one skipped full-pad tile: zero its A frags
        an[NTC / 2][(NTC & 1) * 2 + 0] = 0u;
        an[NTC / 2][(NTC & 1) * 2 + 1] = 0u;
    }
}

__global__ void __launch_bounds__(NTH, 1)
expert_kernel(const float* __restrict__ w0, const float* __restrict__ b0,
              const float* __restrict__ w1, const float* __restrict__ b1,
              const float* __restrict__ w2, const float* __restrict__ b2,
              const float* __restrict__ w3, const float* __restrict__ b3,
              const float* __restrict__ w4, const float* __restrict__ b4,
              const float* __restrict__ head_w, const float* __restrict__ head_b,
              float* __restrict__ out) {
    extern __shared__ char sm[];
    const uint32_t sb = smem_u32(sm);
    const int k = blockIdx.x;
    const int grp = blockIdx.y;
    const int tid = threadIdx.x;
    const int lane = tid & 31;
    const int wid = tid >> 5;

    {
        float* bm = reinterpret_cast<float*>(sm + SM_BIAS);
        const float* bs[5] = {b0, b1, b2, b3, b4};
        const int ntrue[5] = {72, 86, 86, 71, 59};
        const int npad[5] = {80, 96, 96, 80, 64};
        const int boff[5] = {0, 80, 176, 272, 352};
        #pragma unroll
        for (int L = 0; L < 5; ++L) {
            const float* src = bs[L] + k * ntrue[L];
            for (int i = tid; i < npad[L]; i += NTH)
                bm[boff[L] + i] = (i < ntrue[L]) ? src[i] : 0.0f;
        }
        float* hwm = reinterpret_cast<float*>(sm + SM_HW);
        for (int i = tid; i < 64; i += NTH)
            hwm[i] = (i < 59) ? head_w[i] : 0.0f;
    }
    stage_w(sm, w0 + k * 60 * 72, 60, 72, 80,  72, WO0, tid);
    stage_w(sm, w1 + k * 72 * 86, 72, 86, 96,  88, WO1, tid);
    stage_w(sm, w2 + k * 86 * 86, 86, 86, 96, 104, WO2, tid);
    stage_w(sm, w3 + k * 86 * 71, 86, 71, 80, 104, WO3, tid);
    stage_w(sm, w4 + k * 71 * 59, 71, 59, 64,  88, WO4, tid);
    __syncthreads();

    const float hb = head_b[0];
    const float* bm = reinterpret_cast<const float*>(sm + SM_BIAS);
    const float* hwm = reinterpret_cast<const float*>(sm + SM_HW);
    const int g = lane >> 2;
    const int col0 = 2 * (lane & 3);

    uint32_t A0[6][4], A1[6][4];

    for (int tt = wid; tt < TPG; tt += NWARP) {
        const int tile = grp * TPG + tt;
        if (tile >= NTILE) continue;
        const int m0 = tile * 16;

        {
            const char* h0p = (const char*)(g_imh + (m0 + g) * 64 + col0);
            const char* h8p = (const char*)(g_imh + (m0 + g + 8) * 64 + col0);
            #pragma unroll
            for (int j = 0; j < 4; ++j) {
                A0[j][0] = *(const uint32_t*)(h0p + j * 32);
                A0[j][1] = *(const uint32_t*)(h8p + j * 32);
                A0[j][2] = *(const uint32_t*)(h0p + j * 32 + 16);
                A0[j][3] = *(const uint32_t*)(h8p + j * 32 + 16);
            }
        }

        float p0 = 0.0f, p1 = 0.0f;
        do_layer<4, 10,  9,  72, false>(A0, A1,
            sb + SM_WHI + WO0 * 2, sb + SM_WLO + WO0 * 2, bm + 0,   hwm, lane, p0, p1);
        do_layer<5, 12, 11,  88, false>(A1, A0,
            sb + SM_WHI + WO1 * 2, sb + SM_WLO + WO1 * 2, bm + 80,  hwm, lane, p0, p1);
        do_layer<6, 12, 11, 104, false>(A0, A1,
            sb + SM_WHI + WO2 * 2, sb + SM_WLO + WO2 * 2, bm + 176, hwm, lane, p0, p1);
        do_layer<6, 10,  9, 104, false>(A1, A0,
            sb + SM_WHI + WO3 * 2, sb + SM_WLO + WO3 * 2, bm + 272, hwm, lane, p0, p1);
        do_layer<5,  8,  8,  88, true >(A0, A1,
            sb + SM_WHI + WO4 * 2, sb + SM_WLO + WO4 * 2, bm + 352, hwm, lane, p0, p1);

        // head reduce: lanes {4g..4g+3} hold cols of rows g and g+8
        p0 += __shfl_xor_sync(0xffffffffu, p0, 1);
        p0 += __shfl_xor_sync(0xffffffffu, p0, 2);
        p1 += __shfl_xor_sync(0xffffffffu, p1, 1);
        p1 += __shfl_xor_sync(0xffffffffu, p1, 2);
        if ((lane & 3) == 0) {
            int m = m0 + g;
            int b = m / NOUT, p = m - b * NOUT;
            out[(b * NK + k) * NOUT + p] = p0 + hb;
            m += 8;
            b = m / NOUT; p = m - b * NOUT;
            out[(b * NK + k) * NOUT + p] = p1 + hb;
        }
    }
}

extern "C" void kernel_launch(void* const* d_in, const int* in_sizes, int n_in,
                              void* d_out, int out_size) {
    const float* x      = (const float*)d_in[0];
    const float* w0     = (const float*)d_in[1];
    const float* b0     = (const float*)d_in[2];
    const float* w1     = (const float*)d_in[3];
    const float* b1     = (const float*)d_in[4];
    const float* w2     = (const float*)d_in[5];
    const float* b2     = (const float*)d_in[6];
    const float* w3     = (const float*)d_in[7];
    const float* b3     = (const float*)d_in[8];
    const float* w4     = (const float*)d_in[9];
    const float* b4     = (const float*)d_in[10];
    const float* head_w = (const float*)d_in[11];
    const float* head_b = (const float*)d_in[12];
    float* out = (float*)d_out;

    im2col_kernel<<<(MTOT * 64 + 255) / 256, 256>>>(x);

    cudaFuncSetAttribute(expert_kernel,
                         cudaFuncAttributeMaxDynamicSharedMemorySize, SMEM_TOTAL);
    dim3 grid(NK, NGRP);
    expert_kernel<<<grid, NTH, SMEM_TOTAL>>>(
        w0, b0, w1, b1, w2, b2, w3, b3, w4, b4, head_w, head_b, out);
}